// round 6
// baseline (speedup 1.0000x reference)
#include <cuda_runtime.h>
#include <cstdint>
#include <cstddef>

// Problem constants
#define BB 2
#define NN 2048
#define CC 1024
#define HH 16
#define DD 64
#define QK_SCALE 0.125f   // 64^-0.5

// Scratch (device globals: no allocation allowed)
__device__ float g_Q[(size_t)BB * HH * DD * NN];  // [b*16+h][d][tok]  (pre-scaled by QK_SCALE)
__device__ float g_K[(size_t)BB * HH * DD * NN];  // [b*16+h][d][tok]
__device__ float g_V[(size_t)BB * HH * NN * DD];  // [b*16+h][tok][d]
__device__ float g_O[(size_t)BB * NN * CC];       // [b*N+tok][h*64+d]

// ---------------------------------------------------------------------------
// Tiled SGEMM: C[4096 x Ncols] = A[4096 x Kdim] @ W[Kdim x Ncols]
// Block tile 128x128, K-tile 16, 256 threads, 8x8 microtile per thread.
// MODE 0: QKV epilogue -> scatter into g_Q (scaled) / g_K / g_V
// MODE 1: proj epilogue -> Out = acc + bias
// ---------------------------------------------------------------------------
template <int MODE>
__global__ void __launch_bounds__(256)
gemm128(const float* __restrict__ A, const float* __restrict__ W,
        const float* __restrict__ bias, float* __restrict__ Out,
        int Kdim, int Ncols)
{
    __shared__ float As[16][132];   // transposed A tile: As[k][m], padded
    __shared__ float Bs[16][128];   // B tile: Bs[k][n]

    const int tid = threadIdx.x;
    const int tx = tid & 15;        // 0..15 -> columns
    const int ty = tid >> 4;        // 0..15 -> rows
    const int m0 = blockIdx.y * 128;
    const int n0 = blockIdx.x * 128;

    float acc[8][8];
#pragma unroll
    for (int i = 0; i < 8; i++)
#pragma unroll
        for (int j = 0; j < 8; j++) acc[i][j] = 0.f;

    for (int k0 = 0; k0 < Kdim; k0 += 16) {
        // Load A tile (128 rows x 16 k) and store transposed
#pragma unroll
        for (int l = 0; l < 2; l++) {
            int e = tid + l * 256;
            int row = e >> 2;
            int kq = (e & 3) << 2;
            float4 v = *(const float4*)(A + (size_t)(m0 + row) * Kdim + k0 + kq);
            As[kq + 0][row] = v.x;
            As[kq + 1][row] = v.y;
            As[kq + 2][row] = v.z;
            As[kq + 3][row] = v.w;
        }
        // Load B tile (16 k x 128 n), natural layout
#pragma unroll
        for (int l = 0; l < 2; l++) {
            int e = tid + l * 256;
            int kr = e >> 5;
            int nq = (e & 31) << 2;
            *(float4*)&Bs[kr][nq] =
                *(const float4*)(W + (size_t)(k0 + kr) * Ncols + n0 + nq);
        }
        __syncthreads();

#pragma unroll 8
        for (int k = 0; k < 16; k++) {
            float4 a0 = *(const float4*)&As[k][4 * ty];
            float4 a1 = *(const float4*)&As[k][64 + 4 * ty];
            float4 b0 = *(const float4*)&Bs[k][4 * tx];
            float4 b1 = *(const float4*)&Bs[k][64 + 4 * tx];
            float av[8] = {a0.x, a0.y, a0.z, a0.w, a1.x, a1.y, a1.z, a1.w};
            float bv[8] = {b0.x, b0.y, b0.z, b0.w, b1.x, b1.y, b1.z, b1.w};
#pragma unroll
            for (int i = 0; i < 8; i++)
#pragma unroll
                for (int j = 0; j < 8; j++)
                    acc[i][j] = fmaf(av[i], bv[j], acc[i][j]);
        }
        __syncthreads();
    }

    if (MODE == 0) {
        // QKV scatter. Each 128-col block lies fully inside one of {Q,K,V}
        // (1024 % 128 == 0) and fully inside one batch (2048 % 128 == 0).
        const int t = n0 >> 10;          // 0=Q 1=K 2=V
        const int nb = n0 & 1023;        // column base within C
        const int b = m0 >> 11;
        const int tokb = m0 & 2047;
        if (t < 2) {
            float* dst = (t == 0) ? g_Q : g_K;
            const float scale = (t == 0) ? QK_SCALE : 1.0f;
            // layout [bh][d][tok]: vectorize over tokens (rows, 4ty..4ty+3)
#pragma unroll
            for (int jg = 0; jg < 2; jg++) {
#pragma unroll
                for (int j = 0; j < 4; j++) {
                    int cn = nb + jg * 64 + 4 * tx + j;
                    int h = cn >> 6;
                    int d = cn & 63;
                    size_t base = ((size_t)(b * 16 + h) * 64 + d) * 2048;
#pragma unroll
                    for (int ig = 0; ig < 2; ig++) {
                        int tok = tokb + ig * 64 + 4 * ty;
                        float4 v;
                        v.x = acc[ig * 4 + 0][jg * 4 + j] * scale;
                        v.y = acc[ig * 4 + 1][jg * 4 + j] * scale;
                        v.z = acc[ig * 4 + 2][jg * 4 + j] * scale;
                        v.w = acc[ig * 4 + 3][jg * 4 + j] * scale;
                        *(float4*)&dst[base + tok] = v;
                    }
                }
            }
        } else {
            // V layout [bh][tok][d]: vectorize over d (cols, 4tx..4tx+3)
#pragma unroll
            for (int ig = 0; ig < 2; ig++) {
#pragma unroll
                for (int i = 0; i < 4; i++) {
                    int tok = tokb + ig * 64 + 4 * ty + i;
#pragma unroll
                    for (int jg = 0; jg < 2; jg++) {
                        int cn0 = nb + jg * 64 + 4 * tx;
                        int h = cn0 >> 6;
                        int d0 = cn0 & 63;
                        float4 v = make_float4(acc[ig * 4 + i][jg * 4 + 0],
                                               acc[ig * 4 + i][jg * 4 + 1],
                                               acc[ig * 4 + i][jg * 4 + 2],
                                               acc[ig * 4 + i][jg * 4 + 3]);
                        *(float4*)&g_V[((size_t)(b * 16 + h) * 2048 + tok) * 64 + d0] = v;
                    }
                }
            }
        }
    } else {
        // proj epilogue: Out[m][n] = acc + bias[n]
#pragma unroll
        for (int ig = 0; ig < 2; ig++) {
#pragma unroll
            for (int i = 0; i < 4; i++) {
                int gm = m0 + ig * 64 + 4 * ty + i;
#pragma unroll
                for (int jg = 0; jg < 2; jg++) {
                    int cn = n0 + jg * 64 + 4 * tx;
                    float4 bb = *(const float4*)&bias[cn];
                    float4 v = make_float4(acc[ig * 4 + i][jg * 4 + 0] + bb.x,
                                           acc[ig * 4 + i][jg * 4 + 1] + bb.y,
                                           acc[ig * 4 + i][jg * 4 + 2] + bb.z,
                                           acc[ig * 4 + i][jg * 4 + 3] + bb.w);
                    *(float4*)&Out[(size_t)gm * Ncols + cn] = v;
                }
            }
        }
    }
}

// ---------------------------------------------------------------------------
// Flash attention: one block = one (b,h) x one 64-query tile.
// 256 threads (16x16). Thread (ty,tx) owns rows {4ty+i}, score-cols/dims {4tx+j}.
// Q,K live in gmem d-major -> smem tiles are naturally transposed (Qts[d][r],
// Kts[d][c]); P written transposed Pts[c][r] so both matmuls stream float4,
// conflict-free. Online softmax state (m, l, O 4x4) in registers.
// ---------------------------------------------------------------------------
__global__ void __launch_bounds__(256)
attn64(void)
{
    extern __shared__ float sm[];
    float* Qts = sm;              // [64][64]  Qts[d][r]
    float* Kts = sm + 4096;       // [64][64]  Kts[d][c]
    float* Vs  = sm + 8192;       // [64][64]  Vs[c][d]
    float* Pts = sm + 12288;      // [64][68]  Pts[c][r] (padded)

    const int tid = threadIdx.x;
    const int tx = tid & 15;
    const int ty = tid >> 4;
    const int qtile = blockIdx.x;
    const int bh = blockIdx.y;
    const int q0 = qtile * 64;

    const float* Qg = g_Q + (size_t)bh * DD * NN;
    const float* Kg = g_K + (size_t)bh * DD * NN;
    const float* Vg = g_V + (size_t)bh * NN * DD;

    // Load Q tile (transposed layout already in gmem)
#pragma unroll
    for (int l = 0; l < 4; l++) {
        int e = tid + l * 256;
        int d = e >> 4;
        int rq = (e & 15) << 2;
        *(float4*)&Qts[d * 64 + rq] = *(const float4*)&Qg[(size_t)d * NN + q0 + rq];
    }

    float rowm[4], rowl[4], O[4][4];
#pragma unroll
    for (int i = 0; i < 4; i++) {
        rowm[i] = -3.0e38f;
        rowl[i] = 0.f;
#pragma unroll
        for (int j = 0; j < 4; j++) O[i][j] = 0.f;
    }

    for (int it = 0; it < NN / 64; it++) {
        const int kv0 = it * 64;
        __syncthreads();   // protect prev-iter Pts/Vs reads (and first-iter Q load)
        // Load K tile (transposed in gmem) and V tile (natural)
#pragma unroll
        for (int l = 0; l < 4; l++) {
            int e = tid + l * 256;
            int d = e >> 4;
            int cq = (e & 15) << 2;
            *(float4*)&Kts[d * 64 + cq] = *(const float4*)&Kg[(size_t)d * NN + kv0 + cq];
        }
#pragma unroll
        for (int l = 0; l < 4; l++) {
            int e = tid + l * 256;
            int c = e >> 4;
            int dq = (e & 15) << 2;
            *(float4*)&Vs[c * 64 + dq] = *(const float4*)&Vg[(size_t)(kv0 + c) * 64 + dq];
        }
        __syncthreads();

        // S = Q K^T  (Q pre-scaled)
        float s[4][4];
#pragma unroll
        for (int i = 0; i < 4; i++)
#pragma unroll
            for (int j = 0; j < 4; j++) s[i][j] = 0.f;

#pragma unroll 16
        for (int d = 0; d < 64; d++) {
            float4 q = *(const float4*)&Qts[d * 64 + 4 * ty];
            float4 k = *(const float4*)&Kts[d * 64 + 4 * tx];
            float qv[4] = {q.x, q.y, q.z, q.w};
            float kv[4] = {k.x, k.y, k.z, k.w};
#pragma unroll
            for (int i = 0; i < 4; i++)
#pragma unroll
                for (int j = 0; j < 4; j++)
                    s[i][j] = fmaf(qv[i], kv[j], s[i][j]);
        }

        // Online softmax update (row reductions across the 16 tx lanes;
        // lane = (ty&1)*16 + tx, so xor offsets 1,2,4,8 stay inside the group)
#pragma unroll
        for (int i = 0; i < 4; i++) {
            float mloc = fmaxf(fmaxf(s[i][0], s[i][1]), fmaxf(s[i][2], s[i][3]));
#pragma unroll
            for (int o = 1; o < 16; o <<= 1)
                mloc = fmaxf(mloc, __shfl_xor_sync(0xffffffffu, mloc, o));
            float mnew = fmaxf(rowm[i], mloc);
            float alpha = __expf(rowm[i] - mnew);
            rowm[i] = mnew;
            float ps = 0.f;
#pragma unroll
            for (int j = 0; j < 4; j++) {
                float p = __expf(s[i][j] - mnew);
                s[i][j] = p;
                ps += p;
            }
#pragma unroll
            for (int o = 1; o < 16; o <<= 1)
                ps += __shfl_xor_sync(0xffffffffu, ps, o);
            rowl[i] = rowl[i] * alpha + ps;
#pragma unroll
            for (int j = 0; j < 4; j++) O[i][j] *= alpha;
        }

        // Write P transposed: Pts[c][r], float4 across the 4 owned rows
#pragma unroll
        for (int j = 0; j < 4; j++) {
            float4 v = make_float4(s[0][j], s[1][j], s[2][j], s[3][j]);
            *(float4*)&Pts[(4 * tx + j) * 68 + 4 * ty] = v;
        }
        __syncthreads();

        // O += P V
#pragma unroll 16
        for (int c = 0; c < 64; c++) {
            float4 p = *(const float4*)&Pts[c * 68 + 4 * ty];
            float4 v = *(const float4*)&Vs[c * 64 + 4 * tx];
            float pv[4] = {p.x, p.y, p.z, p.w};
            float vv[4] = {v.x, v.y, v.z, v.w};
#pragma unroll
            for (int i = 0; i < 4; i++)
#pragma unroll
                for (int j = 0; j < 4; j++)
                    O[i][j] = fmaf(pv[i], vv[j], O[i][j]);
        }
    }

    // Normalize and write to g_O as [b*N+tok][h*64+d]
    const int h = bh & 15;
    const int b = bh >> 4;
#pragma unroll
    for (int i = 0; i < 4; i++) {
        float inv = 1.0f / rowl[i];
        int tok = q0 + 4 * ty + i;
        float4 v = make_float4(O[i][0] * inv, O[i][1] * inv,
                               O[i][2] * inv, O[i][3] * inv);
        *(float4*)&g_O[(size_t)(b * NN + tok) * CC + h * 64 + 4 * tx] = v;
    }
}

// ---------------------------------------------------------------------------
extern "C" void kernel_launch(void* const* d_in, const int* in_sizes, int n_in,
                              void* d_out, int out_size)
{
    const float* x      = (const float*)d_in[0];   // [2,2048,1024]
    const float* w_qkv  = (const float*)d_in[1];   // [1024,3072]
    const float* w_proj = (const float*)d_in[2];   // [1024,1024]
    const float* b_proj = (const float*)d_in[3];   // [1024]
    float* out = (float*)d_out;                    // [2,2048,1024]

    // 1) QKV projection + scatter into Q (d-major, scaled) / K (d-major) / V
    gemm128<0><<<dim3(3 * CC / 128, BB * NN / 128), 256>>>(
        x, w_qkv, nullptr, nullptr, CC, 3 * CC);

    // 2) Flash attention
    const int smem_bytes = (64 * 64 * 3 + 64 * 68) * (int)sizeof(float); // 66560
    cudaFuncSetAttribute(attn64, cudaFuncAttributeMaxDynamicSharedMemorySize,
                         smem_bytes);
    attn64<<<dim3(NN / 64, BB * HH), 256, smem_bytes>>>();

    // 3) Output projection + bias
    void* pO = nullptr;
    cudaGetSymbolAddress(&pO, g_O);
    gemm128<1><<<dim3(CC / 128, BB * NN / 128), 256>>>(
        (const float*)pO, w_proj, b_proj, out, CC, CC);
}

// round 7
// speedup vs baseline: 1.0006x; 1.0006x over previous
#include <cuda_runtime.h>
#include <cstdint>
#include <cstddef>

// Problem constants
#define BB 2
#define NN 2048
#define CC 1024
#define HH 16
#define DD 64
#define QK_SCALE 0.125f   // 64^-0.5

// Scratch (device globals: no allocation allowed)
__device__ float g_Q[(size_t)BB * HH * DD * NN];  // [b*16+h][d][tok]  (pre-scaled by QK_SCALE)
__device__ float g_K[(size_t)BB * HH * DD * NN];  // [b*16+h][d][tok]
__device__ float g_V[(size_t)BB * HH * NN * DD];  // [b*16+h][tok][d]
__device__ float g_O[(size_t)BB * NN * CC];       // [b*N+tok][h*64+d]

// ---------------------------------------------------------------------------
// Tiled SGEMM: C[4096 x Ncols] = A[4096 x Kdim] @ W[Kdim x Ncols]
// Block tile 128x128, K-tile 16, 256 threads, 8x8 microtile per thread.
// MODE 0: QKV epilogue -> scatter into g_Q (scaled) / g_K / g_V
// MODE 1: proj epilogue -> Out = acc + bias
// ---------------------------------------------------------------------------
template <int MODE>
__global__ void __launch_bounds__(256)
gemm128(const float* __restrict__ A, const float* __restrict__ W,
        const float* __restrict__ bias, float* __restrict__ Out,
        int Kdim, int Ncols)
{
    __shared__ float As[16][132];   // transposed A tile: As[k][m], padded
    __shared__ float Bs[16][128];   // B tile: Bs[k][n]

    const int tid = threadIdx.x;
    const int tx = tid & 15;        // 0..15 -> columns
    const int ty = tid >> 4;        // 0..15 -> rows
    const int m0 = blockIdx.y * 128;
    const int n0 = blockIdx.x * 128;

    float acc[8][8];
#pragma unroll
    for (int i = 0; i < 8; i++)
#pragma unroll
        for (int j = 0; j < 8; j++) acc[i][j] = 0.f;

    for (int k0 = 0; k0 < Kdim; k0 += 16) {
        // Load A tile (128 rows x 16 k) and store transposed
#pragma unroll
        for (int l = 0; l < 2; l++) {
            int e = tid + l * 256;
            int row = e >> 2;
            int kq = (e & 3) << 2;
            float4 v = *(const float4*)(A + (size_t)(m0 + row) * Kdim + k0 + kq);
            As[kq + 0][row] = v.x;
            As[kq + 1][row] = v.y;
            As[kq + 2][row] = v.z;
            As[kq + 3][row] = v.w;
        }
        // Load B tile (16 k x 128 n), natural layout
#pragma unroll
        for (int l = 0; l < 2; l++) {
            int e = tid + l * 256;
            int kr = e >> 5;
            int nq = (e & 31) << 2;
            *(float4*)&Bs[kr][nq] =
                *(const float4*)(W + (size_t)(k0 + kr) * Ncols + n0 + nq);
        }
        __syncthreads();

#pragma unroll 8
        for (int k = 0; k < 16; k++) {
            float4 a0 = *(const float4*)&As[k][4 * ty];
            float4 a1 = *(const float4*)&As[k][64 + 4 * ty];
            float4 b0 = *(const float4*)&Bs[k][4 * tx];
            float4 b1 = *(const float4*)&Bs[k][64 + 4 * tx];
            float av[8] = {a0.x, a0.y, a0.z, a0.w, a1.x, a1.y, a1.z, a1.w};
            float bv[8] = {b0.x, b0.y, b0.z, b0.w, b1.x, b1.y, b1.z, b1.w};
#pragma unroll
            for (int i = 0; i < 8; i++)
#pragma unroll
                for (int j = 0; j < 8; j++)
                    acc[i][j] = fmaf(av[i], bv[j], acc[i][j]);
        }
        __syncthreads();
    }

    if (MODE == 0) {
        // QKV scatter. Each 128-col block lies fully inside one of {Q,K,V}
        // (1024 % 128 == 0) and fully inside one batch (2048 % 128 == 0).
        const int t = n0 >> 10;          // 0=Q 1=K 2=V
        const int nb = n0 & 1023;        // column base within C
        const int b = m0 >> 11;
        const int tokb = m0 & 2047;
        if (t < 2) {
            float* dst = (t == 0) ? g_Q : g_K;
            const float scale = (t == 0) ? QK_SCALE : 1.0f;
            // layout [bh][d][tok]: vectorize over tokens (rows, 4ty..4ty+3)
#pragma unroll
            for (int jg = 0; jg < 2; jg++) {
#pragma unroll
                for (int j = 0; j < 4; j++) {
                    int cn = nb + jg * 64 + 4 * tx + j;
                    int h = cn >> 6;
                    int d = cn & 63;
                    size_t base = ((size_t)(b * 16 + h) * 64 + d) * 2048;
#pragma unroll
                    for (int ig = 0; ig < 2; ig++) {
                        int tok = tokb + ig * 64 + 4 * ty;
                        float4 v;
                        v.x = acc[ig * 4 + 0][jg * 4 + j] * scale;
                        v.y = acc[ig * 4 + 1][jg * 4 + j] * scale;
                        v.z = acc[ig * 4 + 2][jg * 4 + j] * scale;
                        v.w = acc[ig * 4 + 3][jg * 4 + j] * scale;
                        *(float4*)&dst[base + tok] = v;
                    }
                }
            }
        } else {
            // V layout [bh][tok][d]: vectorize over d (cols, 4tx..4tx+3)
#pragma unroll
            for (int ig = 0; ig < 2; ig++) {
#pragma unroll
                for (int i = 0; i < 4; i++) {
                    int tok = tokb + ig * 64 + 4 * ty + i;
#pragma unroll
                    for (int jg = 0; jg < 2; jg++) {
                        int cn0 = nb + jg * 64 + 4 * tx;
                        int h = cn0 >> 6;
                        int d0 = cn0 & 63;
                        float4 v = make_float4(acc[ig * 4 + i][jg * 4 + 0],
                                               acc[ig * 4 + i][jg * 4 + 1],
                                               acc[ig * 4 + i][jg * 4 + 2],
                                               acc[ig * 4 + i][jg * 4 + 3]);
                        *(float4*)&g_V[((size_t)(b * 16 + h) * 2048 + tok) * 64 + d0] = v;
                    }
                }
            }
        }
    } else {
        // proj epilogue: Out[m][n] = acc + bias[n]
#pragma unroll
        for (int ig = 0; ig < 2; ig++) {
#pragma unroll
            for (int i = 0; i < 4; i++) {
                int gm = m0 + ig * 64 + 4 * ty + i;
#pragma unroll
                for (int jg = 0; jg < 2; jg++) {
                    int cn = n0 + jg * 64 + 4 * tx;
                    float4 bb = *(const float4*)&bias[cn];
                    float4 v = make_float4(acc[ig * 4 + i][jg * 4 + 0] + bb.x,
                                           acc[ig * 4 + i][jg * 4 + 1] + bb.y,
                                           acc[ig * 4 + i][jg * 4 + 2] + bb.z,
                                           acc[ig * 4 + i][jg * 4 + 3] + bb.w);
                    *(float4*)&Out[(size_t)gm * Ncols + cn] = v;
                }
            }
        }
    }
}

// ---------------------------------------------------------------------------
// Flash attention: one block = one (b,h) x one 64-query tile.
// 256 threads (16x16). Thread (ty,tx) owns rows {4ty+i}, score-cols/dims {4tx+j}.
// Q,K live in gmem d-major -> smem tiles are naturally transposed (Qts[d][r],
// Kts[d][c]); P written transposed Pts[c][r] so both matmuls stream float4,
// conflict-free. Online softmax state (m, l, O 4x4) in registers.
// ---------------------------------------------------------------------------
__global__ void __launch_bounds__(256)
attn64(void)
{
    extern __shared__ float sm[];
    float* Qts = sm;              // [64][64]  Qts[d][r]
    float* Kts = sm + 4096;       // [64][64]  Kts[d][c]
    float* Vs  = sm + 8192;       // [64][64]  Vs[c][d]
    float* Pts = sm + 12288;      // [64][68]  Pts[c][r] (padded)

    const int tid = threadIdx.x;
    const int tx = tid & 15;
    const int ty = tid >> 4;
    const int qtile = blockIdx.x;
    const int bh = blockIdx.y;
    const int q0 = qtile * 64;

    const float* Qg = g_Q + (size_t)bh * DD * NN;
    const float* Kg = g_K + (size_t)bh * DD * NN;
    const float* Vg = g_V + (size_t)bh * NN * DD;

    // Load Q tile (transposed layout already in gmem)
#pragma unroll
    for (int l = 0; l < 4; l++) {
        int e = tid + l * 256;
        int d = e >> 4;
        int rq = (e & 15) << 2;
        *(float4*)&Qts[d * 64 + rq] = *(const float4*)&Qg[(size_t)d * NN + q0 + rq];
    }

    float rowm[4], rowl[4], O[4][4];
#pragma unroll
    for (int i = 0; i < 4; i++) {
        rowm[i] = -3.0e38f;
        rowl[i] = 0.f;
#pragma unroll
        for (int j = 0; j < 4; j++) O[i][j] = 0.f;
    }

    for (int it = 0; it < NN / 64; it++) {
        const int kv0 = it * 64;
        __syncthreads();   // protect prev-iter Pts/Vs reads (and first-iter Q load)
        // Load K tile (transposed in gmem) and V tile (natural)
#pragma unroll
        for (int l = 0; l < 4; l++) {
            int e = tid + l * 256;
            int d = e >> 4;
            int cq = (e & 15) << 2;
            *(float4*)&Kts[d * 64 + cq] = *(const float4*)&Kg[(size_t)d * NN + kv0 + cq];
        }
#pragma unroll
        for (int l = 0; l < 4; l++) {
            int e = tid + l * 256;
            int c = e >> 4;
            int dq = (e & 15) << 2;
            *(float4*)&Vs[c * 64 + dq] = *(const float4*)&Vg[(size_t)(kv0 + c) * 64 + dq];
        }
        __syncthreads();

        // S = Q K^T  (Q pre-scaled)
        float s[4][4];
#pragma unroll
        for (int i = 0; i < 4; i++)
#pragma unroll
            for (int j = 0; j < 4; j++) s[i][j] = 0.f;

#pragma unroll 16
        for (int d = 0; d < 64; d++) {
            float4 q = *(const float4*)&Qts[d * 64 + 4 * ty];
            float4 k = *(const float4*)&Kts[d * 64 + 4 * tx];
            float qv[4] = {q.x, q.y, q.z, q.w};
            float kv[4] = {k.x, k.y, k.z, k.w};
#pragma unroll
            for (int i = 0; i < 4; i++)
#pragma unroll
                for (int j = 0; j < 4; j++)
                    s[i][j] = fmaf(qv[i], kv[j], s[i][j]);
        }

        // Online softmax update (row reductions across the 16 tx lanes;
        // lane = (ty&1)*16 + tx, so xor offsets 1,2,4,8 stay inside the group)
#pragma unroll
        for (int i = 0; i < 4; i++) {
            float mloc = fmaxf(fmaxf(s[i][0], s[i][1]), fmaxf(s[i][2], s[i][3]));
#pragma unroll
            for (int o = 1; o < 16; o <<= 1)
                mloc = fmaxf(mloc, __shfl_xor_sync(0xffffffffu, mloc, o));
            float mnew = fmaxf(rowm[i], mloc);
            float alpha = __expf(rowm[i] - mnew);
            rowm[i] = mnew;
            float ps = 0.f;
#pragma unroll
            for (int j = 0; j < 4; j++) {
                float p = __expf(s[i][j] - mnew);
                s[i][j] = p;
                ps += p;
            }
#pragma unroll
            for (int o = 1; o < 16; o <<= 1)
                ps += __shfl_xor_sync(0xffffffffu, ps, o);
            rowl[i] = rowl[i] * alpha + ps;
#pragma unroll
            for (int j = 0; j < 4; j++) O[i][j] *= alpha;
        }

        // Write P transposed: Pts[c][r], float4 across the 4 owned rows
#pragma unroll
        for (int j = 0; j < 4; j++) {
            float4 v = make_float4(s[0][j], s[1][j], s[2][j], s[3][j]);
            *(float4*)&Pts[(4 * tx + j) * 68 + 4 * ty] = v;
        }
        __syncthreads();

        // O += P V
#pragma unroll 16
        for (int c = 0; c < 64; c++) {
            float4 p = *(const float4*)&Pts[c * 68 + 4 * ty];
            float4 v = *(const float4*)&Vs[c * 64 + 4 * tx];
            float pv[4] = {p.x, p.y, p.z, p.w};
            float vv[4] = {v.x, v.y, v.z, v.w};
#pragma unroll
            for (int i = 0; i < 4; i++)
#pragma unroll
                for (int j = 0; j < 4; j++)
                    O[i][j] = fmaf(pv[i], vv[j], O[i][j]);
        }
    }

    // Normalize and write to g_O as [b*N+tok][h*64+d]
    const int h = bh & 15;
    const int b = bh >> 4;
#pragma unroll
    for (int i = 0; i < 4; i++) {
        float inv = 1.0f / rowl[i];
        int tok = q0 + 4 * ty + i;
        float4 v = make_float4(O[i][0] * inv, O[i][1] * inv,
                               O[i][2] * inv, O[i][3] * inv);
        *(float4*)&g_O[(size_t)(b * NN + tok) * CC + h * 64 + 4 * tx] = v;
    }
}

// ---------------------------------------------------------------------------
extern "C" void kernel_launch(void* const* d_in, const int* in_sizes, int n_in,
                              void* d_out, int out_size)
{
    const float* x      = (const float*)d_in[0];   // [2,2048,1024]
    const float* w_qkv  = (const float*)d_in[1];   // [1024,3072]
    const float* w_proj = (const float*)d_in[2];   // [1024,1024]
    const float* b_proj = (const float*)d_in[3];   // [1024]
    float* out = (float*)d_out;                    // [2,2048,1024]

    // 1) QKV projection + scatter into Q (d-major, scaled) / K (d-major) / V
    gemm128<0><<<dim3(3 * CC / 128, BB * NN / 128), 256>>>(
        x, w_qkv, nullptr, nullptr, CC, 3 * CC);

    // 2) Flash attention
    const int smem_bytes = (64 * 64 * 3 + 64 * 68) * (int)sizeof(float); // 66560
    cudaFuncSetAttribute(attn64, cudaFuncAttributeMaxDynamicSharedMemorySize,
                         smem_bytes);
    attn64<<<dim3(NN / 64, BB * HH), 256, smem_bytes>>>();

    // 3) Output projection + bias
    void* pO = nullptr;
    cudaGetSymbolAddress(&pO, g_O);
    gemm128<1><<<dim3(CC / 128, BB * NN / 128), 256>>>(
        (const float*)pO, w_proj, b_proj, out, CC, CC);
}

// round 8
// speedup vs baseline: 1.0027x; 1.0021x over previous
#include <cuda_runtime.h>
#include <cstdint>
#include <cstddef>

// Problem constants
#define BB 2
#define NN 2048
#define CC 1024
#define HH 16
#define DD 64
#define QK_SCALE 0.125f   // 64^-0.5

// Scratch (device globals: no allocation allowed)
__device__ float g_Q[(size_t)BB * HH * DD * NN];  // [b*16+h][d][tok]  (pre-scaled by QK_SCALE)
__device__ float g_K[(size_t)BB * HH * DD * NN];  // [b*16+h][d][tok]
__device__ float g_V[(size_t)BB * HH * NN * DD];  // [b*16+h][tok][d]
__device__ float g_O[(size_t)BB * NN * CC];       // [b*N+tok][h*64+d]

// ---------------------------------------------------------------------------
// Tiled SGEMM: C[4096 x Ncols] = A[4096 x Kdim] @ W[Kdim x Ncols]
// Block tile 128x128, K-tile 16, 256 threads, 8x8 microtile per thread.
// MODE 0: QKV epilogue -> scatter into g_Q (scaled) / g_K / g_V
// MODE 1: proj epilogue -> Out = acc + bias
// ---------------------------------------------------------------------------
template <int MODE>
__global__ void __launch_bounds__(256)
gemm128(const float* __restrict__ A, const float* __restrict__ W,
        const float* __restrict__ bias, float* __restrict__ Out,
        int Kdim, int Ncols)
{
    __shared__ float As[16][132];   // transposed A tile: As[k][m], padded
    __shared__ float Bs[16][128];   // B tile: Bs[k][n]

    const int tid = threadIdx.x;
    const int tx = tid & 15;        // 0..15 -> columns
    const int ty = tid >> 4;        // 0..15 -> rows
    const int m0 = blockIdx.y * 128;
    const int n0 = blockIdx.x * 128;

    float acc[8][8];
#pragma unroll
    for (int i = 0; i < 8; i++)
#pragma unroll
        for (int j = 0; j < 8; j++) acc[i][j] = 0.f;

    for (int k0 = 0; k0 < Kdim; k0 += 16) {
        // Load A tile (128 rows x 16 k) and store transposed
#pragma unroll
        for (int l = 0; l < 2; l++) {
            int e = tid + l * 256;
            int row = e >> 2;
            int kq = (e & 3) << 2;
            float4 v = *(const float4*)(A + (size_t)(m0 + row) * Kdim + k0 + kq);
            As[kq + 0][row] = v.x;
            As[kq + 1][row] = v.y;
            As[kq + 2][row] = v.z;
            As[kq + 3][row] = v.w;
        }
        // Load B tile (16 k x 128 n), natural layout
#pragma unroll
        for (int l = 0; l < 2; l++) {
            int e = tid + l * 256;
            int kr = e >> 5;
            int nq = (e & 31) << 2;
            *(float4*)&Bs[kr][nq] =
                *(const float4*)(W + (size_t)(k0 + kr) * Ncols + n0 + nq);
        }
        __syncthreads();

#pragma unroll 8
        for (int k = 0; k < 16; k++) {
            float4 a0 = *(const float4*)&As[k][4 * ty];
            float4 a1 = *(const float4*)&As[k][64 + 4 * ty];
            float4 b0 = *(const float4*)&Bs[k][4 * tx];
            float4 b1 = *(const float4*)&Bs[k][64 + 4 * tx];
            float av[8] = {a0.x, a0.y, a0.z, a0.w, a1.x, a1.y, a1.z, a1.w};
            float bv[8] = {b0.x, b0.y, b0.z, b0.w, b1.x, b1.y, b1.z, b1.w};
#pragma unroll
            for (int i = 0; i < 8; i++)
#pragma unroll
                for (int j = 0; j < 8; j++)
                    acc[i][j] = fmaf(av[i], bv[j], acc[i][j]);
        }
        __syncthreads();
    }

    if (MODE == 0) {
        // QKV scatter. Each 128-col block lies fully inside one of {Q,K,V}
        // (1024 % 128 == 0) and fully inside one batch (2048 % 128 == 0).
        const int t = n0 >> 10;          // 0=Q 1=K 2=V
        const int nb = n0 & 1023;        // column base within C
        const int b = m0 >> 11;
        const int tokb = m0 & 2047;
        if (t < 2) {
            float* dst = (t == 0) ? g_Q : g_K;
            const float scale = (t == 0) ? QK_SCALE : 1.0f;
            // layout [bh][d][tok]: vectorize over tokens (rows, 4ty..4ty+3)
#pragma unroll
            for (int jg = 0; jg < 2; jg++) {
#pragma unroll
                for (int j = 0; j < 4; j++) {
                    int cn = nb + jg * 64 + 4 * tx + j;
                    int h = cn >> 6;
                    int d = cn & 63;
                    size_t base = ((size_t)(b * 16 + h) * 64 + d) * 2048;
#pragma unroll
                    for (int ig = 0; ig < 2; ig++) {
                        int tok = tokb + ig * 64 + 4 * ty;
                        float4 v;
                        v.x = acc[ig * 4 + 0][jg * 4 + j] * scale;
                        v.y = acc[ig * 4 + 1][jg * 4 + j] * scale;
                        v.z = acc[ig * 4 + 2][jg * 4 + j] * scale;
                        v.w = acc[ig * 4 + 3][jg * 4 + j] * scale;
                        *(float4*)&dst[base + tok] = v;
                    }
                }
            }
        } else {
            // V layout [bh][tok][d]: vectorize over d (cols, 4tx..4tx+3)
#pragma unroll
            for (int ig = 0; ig < 2; ig++) {
#pragma unroll
                for (int i = 0; i < 4; i++) {
                    int tok = tokb + ig * 64 + 4 * ty + i;
#pragma unroll
                    for (int jg = 0; jg < 2; jg++) {
                        int cn0 = nb + jg * 64 + 4 * tx;
                        int h = cn0 >> 6;
                        int d0 = cn0 & 63;
                        float4 v = make_float4(acc[ig * 4 + i][jg * 4 + 0],
                                               acc[ig * 4 + i][jg * 4 + 1],
                                               acc[ig * 4 + i][jg * 4 + 2],
                                               acc[ig * 4 + i][jg * 4 + 3]);
                        *(float4*)&g_V[((size_t)(b * 16 + h) * 2048 + tok) * 64 + d0] = v;
                    }
                }
            }
        }
    } else {
        // proj epilogue: Out[m][n] = acc + bias[n]
#pragma unroll
        for (int ig = 0; ig < 2; ig++) {
#pragma unroll
            for (int i = 0; i < 4; i++) {
                int gm = m0 + ig * 64 + 4 * ty + i;
#pragma unroll
                for (int jg = 0; jg < 2; jg++) {
                    int cn = n0 + jg * 64 + 4 * tx;
                    float4 bb = *(const float4*)&bias[cn];
                    float4 v = make_float4(acc[ig * 4 + i][jg * 4 + 0] + bb.x,
                                           acc[ig * 4 + i][jg * 4 + 1] + bb.y,
                                           acc[ig * 4 + i][jg * 4 + 2] + bb.z,
                                           acc[ig * 4 + i][jg * 4 + 3] + bb.w);
                    *(float4*)&Out[(size_t)gm * Ncols + cn] = v;
                }
            }
        }
    }
}

// ---------------------------------------------------------------------------
// Flash attention: one block = one (b,h) x one 64-query tile.
// 256 threads (16x16). Thread (ty,tx) owns rows {4ty+i}, score-cols/dims {4tx+j}.
// Q,K live in gmem d-major -> smem tiles are naturally transposed (Qts[d][r],
// Kts[d][c]); P written transposed Pts[c][r] so both matmuls stream float4,
// conflict-free. Online softmax state (m, l, O 4x4) in registers.
// ---------------------------------------------------------------------------
__global__ void __launch_bounds__(256)
attn64(void)
{
    extern __shared__ float sm[];
    float* Qts = sm;              // [64][64]  Qts[d][r]
    float* Kts = sm + 4096;       // [64][64]  Kts[d][c]
    float* Vs  = sm + 8192;       // [64][64]  Vs[c][d]
    float* Pts = sm + 12288;      // [64][68]  Pts[c][r] (padded)

    const int tid = threadIdx.x;
    const int tx = tid & 15;
    const int ty = tid >> 4;
    const int qtile = blockIdx.x;
    const int bh = blockIdx.y;
    const int q0 = qtile * 64;

    const float* Qg = g_Q + (size_t)bh * DD * NN;
    const float* Kg = g_K + (size_t)bh * DD * NN;
    const float* Vg = g_V + (size_t)bh * NN * DD;

    // Load Q tile (transposed layout already in gmem)
#pragma unroll
    for (int l = 0; l < 4; l++) {
        int e = tid + l * 256;
        int d = e >> 4;
        int rq = (e & 15) << 2;
        *(float4*)&Qts[d * 64 + rq] = *(const float4*)&Qg[(size_t)d * NN + q0 + rq];
    }

    float rowm[4], rowl[4], O[4][4];
#pragma unroll
    for (int i = 0; i < 4; i++) {
        rowm[i] = -3.0e38f;
        rowl[i] = 0.f;
#pragma unroll
        for (int j = 0; j < 4; j++) O[i][j] = 0.f;
    }

    for (int it = 0; it < NN / 64; it++) {
        const int kv0 = it * 64;
        __syncthreads();   // protect prev-iter Pts/Vs reads (and first-iter Q load)
        // Load K tile (transposed in gmem) and V tile (natural)
#pragma unroll
        for (int l = 0; l < 4; l++) {
            int e = tid + l * 256;
            int d = e >> 4;
            int cq = (e & 15) << 2;
            *(float4*)&Kts[d * 64 + cq] = *(const float4*)&Kg[(size_t)d * NN + kv0 + cq];
        }
#pragma unroll
        for (int l = 0; l < 4; l++) {
            int e = tid + l * 256;
            int c = e >> 4;
            int dq = (e & 15) << 2;
            *(float4*)&Vs[c * 64 + dq] = *(const float4*)&Vg[(size_t)(kv0 + c) * 64 + dq];
        }
        __syncthreads();

        // S = Q K^T  (Q pre-scaled)
        float s[4][4];
#pragma unroll
        for (int i = 0; i < 4; i++)
#pragma unroll
            for (int j = 0; j < 4; j++) s[i][j] = 0.f;

#pragma unroll 16
        for (int d = 0; d < 64; d++) {
            float4 q = *(const float4*)&Qts[d * 64 + 4 * ty];
            float4 k = *(const float4*)&Kts[d * 64 + 4 * tx];
            float qv[4] = {q.x, q.y, q.z, q.w};
            float kv[4] = {k.x, k.y, k.z, k.w};
#pragma unroll
            for (int i = 0; i < 4; i++)
#pragma unroll
                for (int j = 0; j < 4; j++)
                    s[i][j] = fmaf(qv[i], kv[j], s[i][j]);
        }

        // Online softmax update (row reductions across the 16 tx lanes;
        // lane = (ty&1)*16 + tx, so xor offsets 1,2,4,8 stay inside the group)
#pragma unroll
        for (int i = 0; i < 4; i++) {
            float mloc = fmaxf(fmaxf(s[i][0], s[i][1]), fmaxf(s[i][2], s[i][3]));
#pragma unroll
            for (int o = 1; o < 16; o <<= 1)
                mloc = fmaxf(mloc, __shfl_xor_sync(0xffffffffu, mloc, o));
            float mnew = fmaxf(rowm[i], mloc);
            float alpha = __expf(rowm[i] - mnew);
            rowm[i] = mnew;
            float ps = 0.f;
#pragma unroll
            for (int j = 0; j < 4; j++) {
                float p = __expf(s[i][j] - mnew);
                s[i][j] = p;
                ps += p;
            }
#pragma unroll
            for (int o = 1; o < 16; o <<= 1)
                ps += __shfl_xor_sync(0xffffffffu, ps, o);
            rowl[i] = rowl[i] * alpha + ps;
#pragma unroll
            for (int j = 0; j < 4; j++) O[i][j] *= alpha;
        }

        // Write P transposed: Pts[c][r], float4 across the 4 owned rows
#pragma unroll
        for (int j = 0; j < 4; j++) {
            float4 v = make_float4(s[0][j], s[1][j], s[2][j], s[3][j]);
            *(float4*)&Pts[(4 * tx + j) * 68 + 4 * ty] = v;
        }
        __syncthreads();

        // O += P V
#pragma unroll 16
        for (int c = 0; c < 64; c++) {
            float4 p = *(const float4*)&Pts[c * 68 + 4 * ty];
            float4 v = *(const float4*)&Vs[c * 64 + 4 * tx];
            float pv[4] = {p.x, p.y, p.z, p.w};
            float vv[4] = {v.x, v.y, v.z, v.w};
#pragma unroll
            for (int i = 0; i < 4; i++)
#pragma unroll
                for (int j = 0; j < 4; j++)
                    O[i][j] = fmaf(pv[i], vv[j], O[i][j]);
        }
    }

    // Normalize and write to g_O as [b*N+tok][h*64+d]
    const int h = bh & 15;
    const int b = bh >> 4;
#pragma unroll
    for (int i = 0; i < 4; i++) {
        float inv = 1.0f / rowl[i];
        int tok = q0 + 4 * ty + i;
        float4 v = make_float4(O[i][0] * inv, O[i][1] * inv,
                               O[i][2] * inv, O[i][3] * inv);
        *(float4*)&g_O[(size_t)(b * NN + tok) * CC + h * 64 + 4 * tx] = v;
    }
}

// ---------------------------------------------------------------------------
extern "C" void kernel_launch(void* const* d_in, const int* in_sizes, int n_in,
                              void* d_out, int out_size)
{
    const float* x      = (const float*)d_in[0];   // [2,2048,1024]
    const float* w_qkv  = (const float*)d_in[1];   // [1024,3072]
    const float* w_proj = (const float*)d_in[2];   // [1024,1024]
    const float* b_proj = (const float*)d_in[3];   // [1024]
    float* out = (float*)d_out;                    // [2,2048,1024]

    // 1) QKV projection + scatter into Q (d-major, scaled) / K (d-major) / V
    gemm128<0><<<dim3(3 * CC / 128, BB * NN / 128), 256>>>(
        x, w_qkv, nullptr, nullptr, CC, 3 * CC);

    // 2) Flash attention
    const int smem_bytes = (64 * 64 * 3 + 64 * 68) * (int)sizeof(float); // 66560
    cudaFuncSetAttribute(attn64, cudaFuncAttributeMaxDynamicSharedMemorySize,
                         smem_bytes);
    attn64<<<dim3(NN / 64, BB * HH), 256, smem_bytes>>>();

    // 3) Output projection + bias
    void* pO = nullptr;
    cudaGetSymbolAddress(&pO, g_O);
    gemm128<1><<<dim3(CC / 128, BB * NN / 128), 256>>>(
        (const float*)pO, w_proj, b_proj, out, CC, CC);
}